// round 4
// baseline (speedup 1.0000x reference)
#include <cuda_runtime.h>

typedef unsigned long long u64t;

// ---- packed f32x2 helpers (sm_103a) ----
__device__ __forceinline__ u64t pack2(float x, float y){
    u64t r; asm("mov.b64 %0,{%1,%2};" : "=l"(r) : "f"(x), "f"(y)); return r;
}
__device__ __forceinline__ float2 unpack2(u64t a){
    float2 r; asm("mov.b64 {%0,%1},%2;" : "=f"(r.x), "=f"(r.y) : "l"(a)); return r;
}
__device__ __forceinline__ u64t fma2_(u64t a, u64t b, u64t c){
    u64t d; asm("fma.rn.f32x2 %0,%1,%2,%3;" : "=l"(d) : "l"(a), "l"(b), "l"(c)); return d;
}
__device__ __forceinline__ u64t mul2_(u64t a, u64t b){
    u64t d; asm("mul.rn.f32x2 %0,%1,%2;" : "=l"(d) : "l"(a), "l"(b)); return d;
}
__device__ __forceinline__ u64t add2_(u64t a, u64t b){
    u64t d; asm("add.rn.f32x2 %0,%1,%2;" : "=l"(d) : "l"(a), "l"(b)); return d;
}

#define NB   32      // batches
#define NI   4096    // input capsules
#define NO   32      // output capsules
#define CI   32      // i per block
#define NBLK 128     // NI / CI  (<= SM count: all blocks co-resident)
#define WPB  8       // warps per block
#define IPW  4       // i per warp
#define PSTRIDE (NB * NO * 16)   // 16384 floats per partial slab

// scratch (static device globals — no allocations)
__device__ __align__(16) float g_part[NBLK * PSTRIDE];   // 8 MB partials
__device__ __align__(16) float g_v[NB * NO * 16];        // v used for logits this pass
__device__ unsigned g_count = 0;
__device__ unsigned g_sense = 0;

// ---------------------------------------------------------------------------
// Sense-reversing grid barrier. All NBLK blocks are co-resident (grid<=SMs).
// Integer atomics only -> deterministic. g_count self-resets; g_sense grows
// monotonically (safe across graph replays with != comparison).
// ---------------------------------------------------------------------------
__device__ __forceinline__ void gbar()
{
    __threadfence();               // publish this thread's global stores
    __syncthreads();
    if (threadIdx.x == 0) {
        unsigned my = *(volatile unsigned*)&g_sense;
        unsigned prev = atomicAdd(&g_count, 1u);
        if (prev == NBLK - 1u) {
            atomicExch(&g_count, 0u);
            __threadfence();
            atomicAdd(&g_sense, 1u);
        } else {
            while (*(volatile unsigned*)&g_sense == my) { __nanosleep(32); }
        }
        __threadfence();           // acquire
    }
    __syncthreads();
}

// ---------------------------------------------------------------------------
// One routing pass: lane = o, warp = 4 i's, loop over 32 batches.
// Accumulates s partials into g_part[blk][b][o][16].
// ---------------------------------------------------------------------------
template<bool FIRST>
__device__ __forceinline__ void run_pass(const float* __restrict__ poses,
                                         const u64t (&W)[IPW][8],
                                         u64t (*Ps)[CI * 16],
                                         u64t (*red)[NO][9],
                                         int tid, int lane, int warp, int blk)
{
    const int o = lane;

    // stage poses for batch b into shared (each scalar duplicated to both halves)
    auto stageP = [&](int b, int buf) {
        const float2* src = (const float2*)(poses + ((size_t)b * NI + (size_t)blk * CI) * 16);
        float2 pv = src[tid];
        Ps[buf][2 * tid]     = pack2(pv.x, pv.x);
        Ps[buf][2 * tid + 1] = pack2(pv.y, pv.y);
    };

    stageP(0, 0);
    __syncthreads();

    for (int b = 0; b < NB; b++) {
        u64t vreg[8];
        if (!FIRST) {
            // g_v written by another SM last phase: bypass L1 (L2 is coherent)
            const float4* gv = (const float4*)(g_v + ((size_t)b * NO + o) * 16);
            #pragma unroll
            for (int q4 = 0; q4 < 4; q4++) {
                float4 a = __ldcg(gv + q4);
                vreg[2 * q4]     = pack2(a.x, a.y);
                vreg[2 * q4 + 1] = pack2(a.z, a.w);
            }
        }

        u64t sacc[8];
        #pragma unroll
        for (int q = 0; q < 8; q++) sacc[q] = 0ull;

        const u64t* Pb = Ps[b & 1];

        #pragma unroll
        for (int j = 0; j < IPW; j++) {
            const u64t* Pi = Pb + (warp * IPW + j) * 16;
            // votes V[x][zpair] = sum_y P[x][y] * W[y][zpair]
            u64t V[8];
            #pragma unroll
            for (int x = 0; x < 4; x++) {
                u64t p0 = Pi[x * 4 + 0];
                V[2 * x]     = mul2_(p0, W[j][0]);
                V[2 * x + 1] = mul2_(p0, W[j][1]);
                #pragma unroll
                for (int y = 1; y < 4; y++) {
                    u64t p = Pi[x * 4 + y];
                    V[2 * x]     = fma2_(p, W[j][2 * y],     V[2 * x]);
                    V[2 * x + 1] = fma2_(p, W[j][2 * y + 1], V[2 * x + 1]);
                }
            }

            if (FIRST) {
                #pragma unroll
                for (int q = 0; q < 8; q++) sacc[q] = add2_(sacc[q], V[q]);
            } else {
                u64t d = mul2_(V[0], vreg[0]);
                #pragma unroll
                for (int q = 1; q < 8; q++) d = fma2_(V[q], vreg[q], d);
                float2 dd = unpack2(d);
                float e = __expf(dd.x + dd.y);
                float den = e;
                #pragma unroll
                for (int sh = 16; sh > 0; sh >>= 1)
                    den += __shfl_xor_sync(0xffffffffu, den, sh);
                float c = __fdividef(e, den);
                u64t cp = pack2(c, c);
                #pragma unroll
                for (int q = 0; q < 8; q++) sacc[q] = fma2_(cp, V[q], sacc[q]);
            }
        }

        #pragma unroll
        for (int q = 0; q < 8; q++) red[warp][o][q] = sacc[q];
        if (b + 1 < NB) stageP(b + 1, (b + 1) & 1);
        __syncthreads();

        // cross-warp reduce: thread -> (oo = tid>>3, q = tid&7)
        {
            int oo = tid >> 3, q = tid & 7;
            u64t a = red[0][oo][q];
            #pragma unroll
            for (int ww = 1; ww < WPB; ww++) a = add2_(a, red[ww][oo][q]);
            float2 av = unpack2(a);
            float2* gp = (float2*)(g_part + ((size_t)blk * NB + b) * NO * 16);
            gp[oo * 8 + q] = av;
        }
        __syncthreads();
    }
}

// ---------------------------------------------------------------------------
// Reduce over 128 partial slabs + squash. Each block owns 128 contiguous
// output elements (tid<128 active), one thread per element; partials are L2-hot.
// vsum (running v0) lives in a register across phases (same thread, same elem).
// ---------------------------------------------------------------------------
template<int PHASE>
__device__ __forceinline__ void run_reduce(float* __restrict__ out, float& vsum,
                                           int tid, int blk)
{
    if (tid < 128) {
        int t = blk * 128 + tid;           // t = b*512 + o*16 + k
        float s = 0.f;
        const float* p = g_part + t;
        #pragma unroll 16
        for (int q = 0; q < NBLK; q++) s += __ldcg(p + (size_t)q * PSTRIDE);
        if (PHASE == 0) s *= (1.0f / 32.0f);   // uniform c on iter 0

        float n2 = s * s;
        #pragma unroll
        for (int sh = 1; sh < 16; sh <<= 1)
            n2 += __shfl_xor_sync(0xffffffffu, n2, sh);  // sum over 16 pose elems

        float n = sqrtf(n2 + 1e-12f);
        float f = n2 / ((1.0f + n2) * n);
        float v = s * f;

        if (PHASE == 0)      { g_v[t] = v; vsum = v; }
        else if (PHASE == 1) { g_v[t] = vsum + v; }
        else {
            out[t] = v;
            if ((t & 15) == 0)
                out[NB * NO * 16 + (t >> 4)] = sqrtf(n2 * f * f + 1e-12f);
        }
    }
}

// ---------------------------------------------------------------------------
// Fully fused persistent kernel: 3 pass phases + 3 reduce phases, 5 grid
// barriers, everything stays in L2.
// ---------------------------------------------------------------------------
__global__ __launch_bounds__(256) void caps_fused(const float* __restrict__ poses,
                                                  const float* __restrict__ w,
                                                  float* __restrict__ out)
{
    __shared__ u64t Ps[2][CI * 16];
    __shared__ u64t red[WPB][NO][9];

    const int tid  = threadIdx.x;
    const int lane = tid & 31;
    const int warp = tid >> 5;
    const int blk  = blockIdx.x;
    const int o    = lane;

    // W for my 4 i's, register-resident across all phases.
    u64t W[IPW][8];
    {
        const float4* wp = (const float4*)(w + ((size_t)o * NI + (size_t)blk * CI + warp * IPW) * 16);
        #pragma unroll
        for (int j = 0; j < IPW; j++) {
            #pragma unroll
            for (int y = 0; y < 4; y++) {
                float4 t4 = wp[j * 4 + y];
                W[j][2 * y]     = pack2(t4.x, t4.y);
                W[j][2 * y + 1] = pack2(t4.z, t4.w);
            }
        }
    }

    float vsum = 0.f;

    run_pass<true >(poses, W, Ps, red, tid, lane, warp, blk);
    gbar();
    run_reduce<0>(out, vsum, tid, blk);
    gbar();
    run_pass<false>(poses, W, Ps, red, tid, lane, warp, blk);
    gbar();
    run_reduce<1>(out, vsum, tid, blk);
    gbar();
    run_pass<false>(poses, W, Ps, red, tid, lane, warp, blk);
    gbar();
    run_reduce<2>(out, vsum, tid, blk);
}

extern "C" void kernel_launch(void* const* d_in, const int* in_sizes, int n_in,
                              void* d_out, int out_size)
{
    const float* poses = (const float*)d_in[0];
    // d_in[1] = input_activations — unused by the reference math
    const float* w     = (const float*)d_in[2];
    float* out = (float*)d_out;

    caps_fused<<<NBLK, 256>>>(poses, w, out);
}

// round 5
// speedup vs baseline: 1.2999x; 1.2999x over previous
#include <cuda_runtime.h>

typedef unsigned long long u64t;

// ---- packed f32x2 helpers (sm_103a) ----
__device__ __forceinline__ u64t pack2(float x, float y){
    u64t r; asm("mov.b64 %0,{%1,%2};" : "=l"(r) : "f"(x), "f"(y)); return r;
}
__device__ __forceinline__ u64t pack2d(float x){
    u64t r; asm("mov.b64 %0,{%1,%1};" : "=l"(r) : "f"(x)); return r;
}
__device__ __forceinline__ float2 unpack2(u64t a){
    float2 r; asm("mov.b64 {%0,%1},%2;" : "=f"(r.x), "=f"(r.y) : "l"(a)); return r;
}
__device__ __forceinline__ u64t fma2_(u64t a, u64t b, u64t c){
    u64t d; asm("fma.rn.f32x2 %0,%1,%2,%3;" : "=l"(d) : "l"(a), "l"(b), "l"(c)); return d;
}
__device__ __forceinline__ u64t mul2_(u64t a, u64t b){
    u64t d; asm("mul.rn.f32x2 %0,%1,%2;" : "=l"(d) : "l"(a), "l"(b)); return d;
}
__device__ __forceinline__ u64t add2_(u64t a, u64t b){
    u64t d; asm("add.rn.f32x2 %0,%1,%2;" : "=l"(d) : "l"(a), "l"(b)); return d;
}

#define NB     32      // batches
#define NI     4096    // input capsules
#define NO     32      // output capsules
#define CI     32      // i per chunk
#define NCHUNK 128     // NI / CI
#define BG     4       // batch groups (8 warps/block x 4 groups = 32 batches)
#define EL     (NB * NO * 16)      // 16384 output elements
#define PSLAB  EL                  // floats per partial slab

// scratch (static device globals — no allocations)
__device__ __align__(16) u64t  g_wt[NI * 8 * NO];        // transposed W, z-paired: [i][q][o], 8 MB
__device__ __align__(16) float g_part[NCHUNK * PSLAB];   // 8 MB partials: [chunk][b][o][16]
__device__ __align__(16) float g_part2[8 * EL];          // 512 KB stage-2 partials
__device__ __align__(16) float g_v[EL];                  // v for logits this pass
__device__ __align__(16) float g_vsum[EL];               // running sum of v's

// ---------------------------------------------------------------------------
// Transpose W: w[o][i][4][4] -> Wt[i][q][o] (u64 z-pairs, q = y*2 + z/2).
// Coalesced writes; reads strided (absorbed by L2 sectors).
// ---------------------------------------------------------------------------
__global__ __launch_bounds__(256) void wt_kernel(const float* __restrict__ w)
{
    int idx = blockIdx.x * 256 + threadIdx.x;      // (i*8 + q)*32 + o
    int o = idx & 31;
    int q = (idx >> 5) & 7;
    int i = idx >> 8;
    const float2* src = (const float2*)(w + ((size_t)o * NI + i) * 16) + q;
    float2 v = __ldg(src);
    g_wt[idx] = pack2(v.x, v.y);
}

// ---------------------------------------------------------------------------
// Pass kernel: grid (NCHUNK, BG), block 256 = 8 warps.
// Warp owns (batch b = g*8 + warp, chunk c): lane = o, loops all 32 i.
// Poses in registers (lane l holds pose of i=l), broadcast by shuffle.
// No smem, no syncthreads; warp exclusively writes g_part[c][b][o][16].
// ---------------------------------------------------------------------------
template<bool FIRST>
__global__ __launch_bounds__(256, 2) void pass_kernel(const float* __restrict__ poses)
{
    const int tid  = threadIdx.x;
    const int lane = tid & 31;
    const int warp = tid >> 5;
    const int c    = blockIdx.x;
    const int b    = blockIdx.y * 8 + warp;
    const int o    = lane;

    // lane l holds the full 4x4 pose of input capsule i = c*32 + l (batch b)
    float P[16];
    {
        const float4* pp = (const float4*)(poses + ((size_t)b * NI + (size_t)c * CI + lane) * 16);
        #pragma unroll
        for (int x = 0; x < 4; x++) {
            float4 t = pp[x];
            P[4 * x] = t.x; P[4 * x + 1] = t.y; P[4 * x + 2] = t.z; P[4 * x + 3] = t.w;
        }
    }

    // v for the logit dot-product (passes 2,3): per-lane (b, o)
    u64t vreg[8];
    if (!FIRST) {
        const float4* gv = (const float4*)(g_v + ((size_t)b * NO + o) * 16);
        #pragma unroll
        for (int x = 0; x < 4; x++) {
            float4 a = gv[x];
            vreg[2 * x]     = pack2(a.x, a.y);
            vreg[2 * x + 1] = pack2(a.z, a.w);
        }
    }

    u64t sacc[8];
    #pragma unroll
    for (int q = 0; q < 8; q++) sacc[q] = 0ull;

    const u64t* wt = g_wt + ((size_t)c * CI) * 8 * 32 + o;

    #pragma unroll 2
    for (int i = 0; i < CI; i++) {
        // W row for (o, i): 8 coalesced LDG.64
        u64t Wp[8];
        #pragma unroll
        for (int q = 0; q < 8; q++) Wp[q] = wt[(i * 8 + q) * 32];

        // pose of capsule i, broadcast from lane i, duplicated into f32x2 halves
        u64t Pd[16];
        #pragma unroll
        for (int k = 0; k < 16; k++)
            Pd[k] = pack2d(__shfl_sync(0xffffffffu, P[k], i));

        // votes V[x][zpair] = sum_y P[x][y] * W[y][zpair]
        u64t V[8];
        #pragma unroll
        for (int x = 0; x < 4; x++) {
            u64t p0 = Pd[4 * x];
            V[2 * x]     = mul2_(p0, Wp[0]);
            V[2 * x + 1] = mul2_(p0, Wp[1]);
            #pragma unroll
            for (int y = 1; y < 4; y++) {
                u64t p = Pd[4 * x + y];
                V[2 * x]     = fma2_(p, Wp[2 * y],     V[2 * x]);
                V[2 * x + 1] = fma2_(p, Wp[2 * y + 1], V[2 * x + 1]);
            }
        }

        if (FIRST) {
            // c = 1/32 uniform (softmax of zeros); scale applied in rsB
            #pragma unroll
            for (int q = 0; q < 8; q++) sacc[q] = add2_(sacc[q], V[q]);
        } else {
            // logit = <V, v>, softmax over o (= lanes)
            u64t d = mul2_(V[0], vreg[0]);
            #pragma unroll
            for (int q = 1; q < 8; q++) d = fma2_(V[q], vreg[q], d);
            float2 dd = unpack2(d);
            float e = __expf(dd.x + dd.y);     // logits are O(1); no max-shift needed
            float den = e;
            #pragma unroll
            for (int sh = 16; sh > 0; sh >>= 1)
                den += __shfl_xor_sync(0xffffffffu, den, sh);
            float cc = __fdividef(e, den);
            u64t cp = pack2d(cc);
            #pragma unroll
            for (int q = 0; q < 8; q++) sacc[q] = fma2_(cp, V[q], sacc[q]);
        }
    }

    // sole owner of g_part[c][b][o][0..15]
    float4* gp = (float4*)(g_part + (((size_t)c * NB + b) * NO + o) * 16);
    #pragma unroll
    for (int x = 0; x < 4; x++) {
        float2 a = unpack2(sacc[2 * x]);
        float2 bb = unpack2(sacc[2 * x + 1]);
        gp[x] = make_float4(a.x, a.y, bb.x, bb.y);
    }
}

// ---------------------------------------------------------------------------
// rsA: reduce 128 slabs -> 8 partials per element. 131072 threads, coalesced.
// ---------------------------------------------------------------------------
__global__ __launch_bounds__(256) void rsA_kernel()
{
    int idx = blockIdx.x * 256 + threadIdx.x;   // 0 .. 8*EL-1
    int p = idx >> 14;                          // partial group 0..7
    int t = idx & (EL - 1);                     // element
    float s = 0.f;
    const float* gp = g_part + (size_t)(p * 16) * PSLAB + t;
    #pragma unroll
    for (int j = 0; j < 16; j++) s += gp[(size_t)j * PSLAB];
    g_part2[(size_t)p * EL + t] = s;
}

// ---------------------------------------------------------------------------
// rsB: reduce 8 partials + squash. 16384 threads; 16 lanes = one (b,o).
// PHASE 0: v0 -> g_v, g_vsum.  PHASE 1: g_v = v0 + v1.  PHASE 2: write output.
// ---------------------------------------------------------------------------
template<int PHASE>
__global__ __launch_bounds__(256) void rsB_kernel(float* __restrict__ out)
{
    int t = blockIdx.x * 256 + threadIdx.x;     // t = b*512 + o*16 + k
    float s = 0.f;
    #pragma unroll
    for (int p = 0; p < 8; p++) s += g_part2[(size_t)p * EL + t];
    if (PHASE == 0) s *= (1.0f / 32.0f);        // uniform coupling on iter 0

    float n2 = s * s;
    #pragma unroll
    for (int sh = 1; sh < 16; sh <<= 1)
        n2 += __shfl_xor_sync(0xffffffffu, n2, sh);   // sum over 16 pose elems

    float n = sqrtf(n2 + 1e-12f);
    float f = n2 / ((1.0f + n2) * n);
    float v = s * f;

    if (PHASE == 0)      { g_v[t] = v; g_vsum[t] = v; }
    else if (PHASE == 1) { g_v[t] = g_vsum[t] + v; }
    else {
        out[t] = v;                                     // capsule_poses [B,O,4,4]
        if ((t & 15) == 0)
            out[EL + (t >> 4)] = sqrtf(n2 * f * f + 1e-12f);  // activations
    }
}

extern "C" void kernel_launch(void* const* d_in, const int* in_sizes, int n_in,
                              void* d_out, int out_size)
{
    const float* poses = (const float*)d_in[0];
    // d_in[1] = input_activations — unused by the reference math
    const float* w     = (const float*)d_in[2];
    float* out = (float*)d_out;

    dim3 pgrid(NCHUNK, BG);

    wt_kernel<<<NI * 8 * NO / 256, 256>>>(w);

    pass_kernel<true ><<<pgrid, 256>>>(poses);
    rsA_kernel<<<8 * EL / 256, 256>>>();
    rsB_kernel<0><<<EL / 256, 256>>>(nullptr);

    pass_kernel<false><<<pgrid, 256>>>(poses);
    rsA_kernel<<<8 * EL / 256, 256>>>();
    rsB_kernel<1><<<EL / 256, 256>>>(nullptr);

    pass_kernel<false><<<pgrid, 256>>>(poses);
    rsA_kernel<<<8 * EL / 256, 256>>>();
    rsB_kernel<2><<<EL / 256, 256>>>(out);
}